// round 15
// baseline (speedup 1.0000x reference)
#include <cuda_runtime.h>
#include <cuda_bf16.h>
#include <cuda_fp16.h>
#include <cstdint>

#define NN   8192
#define FIN  512
#define FO   256
#define ALPHA 0.2f
#define MASKF 9e-15f

#define KT     64
#define NPART  4

#define WPAIRS (FIN*FO/2)

// Scratch (device globals — no allocation allowed)
__device__ __align__(16) uint32_t g_wb_hi[WPAIRS];
__device__ __align__(16) uint32_t g_wb_lo[WPAIRS];
__device__ __align__(16) uint32_t g_hb_hi[NN * FO / 2];   // fp16x2 [i][f]
__device__ __align__(16) float    g_pn   [NPART * NN * FO];
__device__ __align__(16) float    g_pd   [NPART * NN];
__device__ __align__(16) float    g_f1   [NN];
__device__ __align__(16) float    g_f2   [NN];
__device__ __align__(16) float    g_wa   [2 * FIN];        // W@a1, W@a2
__device__ uint32_t g_m2b[64];                             // bucketed max f2 (fkey)

// ---------------------------------------------------------------------------
// helpers
// ---------------------------------------------------------------------------
__device__ __forceinline__ uint32_t smem_u32(const void* p) {
    uint32_t a;
    asm("{ .reg .u64 t; cvta.to.shared.u64 t, %1; cvt.u32.u64 %0, t; }"
        : "=r"(a) : "l"(p));
    return a;
}
__device__ __forceinline__ uint32_t bfx2(float lo, float hi) {
    uint32_t r;
    asm("cvt.rn.bf16x2.f32 %0, %1, %2;" : "=r"(r) : "f"(hi), "f"(lo));
    return r;
}
__device__ __forceinline__ float bf_lo_f(uint32_t p) { return __uint_as_float(p << 16); }
__device__ __forceinline__ float bf_hi_f(uint32_t p) { return __uint_as_float(p & 0xFFFF0000u); }

__device__ __forceinline__ uint32_t fkey(float f) {
    uint32_t b = __float_as_uint(f);
    return (b & 0x80000000u) ? ~b : (b | 0x80000000u);
}
__device__ __forceinline__ float funkey(uint32_t k) {
    uint32_t b = (k & 0x80000000u) ? (k & 0x7FFFFFFFu) : ~k;
    return __uint_as_float(b);
}

// CTA whose job range contains job T  (16384 jobs = 104 CTAs x56 + 192 x55)
__device__ __forceinline__ int first_cta_of(int T) {
    return (T < 5824) ? (T / 56) : (104 + (T - 5824) / 55);
}

#define CPA16(dst, src) \
    asm volatile("cp.async.cg.shared.global [%0], [%1], 16;" :: "r"(dst), "l"(src) : "memory")
#define CPA_COMMIT() asm volatile("cp.async.commit_group;" ::: "memory")
#define CPA_WAITG(n) asm volatile("cp.async.wait_group %0;" :: "n"(n) : "memory")

#define LDSM4(R0,R1,R2,R3,addr) \
    asm volatile("ldmatrix.sync.aligned.m8n8.x4.shared.b16 {%0,%1,%2,%3}, [%4];" \
        : "=r"(R0), "=r"(R1), "=r"(R2), "=r"(R3) : "r"(addr))
#define LDSM4T(R0,R1,R2,R3,addr) \
    asm volatile("ldmatrix.sync.aligned.m8n8.x4.trans.shared.b16 {%0,%1,%2,%3}, [%4];" \
        : "=r"(R0), "=r"(R1), "=r"(R2), "=r"(R3) : "r"(addr))

#define MMAB(D, a0,a1,a2,a3, b0,b1) \
    asm volatile("mma.sync.aligned.m16n8k16.row.col.f32.bf16.bf16.f32 " \
        "{%0,%1,%2,%3}, {%4,%5,%6,%7}, {%8,%9}, {%0,%1,%2,%3};" \
        : "+f"((D)[0]), "+f"((D)[1]), "+f"((D)[2]), "+f"((D)[3]) \
        : "r"(a0), "r"(a1), "r"(a2), "r"(a3), "r"(b0), "r"(b1))

#define MMAH(D, a0,a1,a2,a3, b0,b1) \
    asm volatile("mma.sync.aligned.m16n8k16.row.col.f32.f16.f16.f32 " \
        "{%0,%1,%2,%3}, {%4,%5,%6,%7}, {%8,%9}, {%0,%1,%2,%3};" \
        : "+f"((D)[0]), "+f"((D)[1]), "+f"((D)[2]), "+f"((D)[3]) \
        : "r"(a0), "r"(a1), "r"(a2), "r"(a3), "r"(b0), "r"(b1))

// ---------------------------------------------------------------------------
// k_conv: split W to bf16 hi/lo; compute wa = W@a1 / W@a2; zero pd/m2b
// ---------------------------------------------------------------------------
__global__ void k_conv(const float* __restrict__ W, const float* __restrict__ a) {
    int t = threadIdx.x, bx = blockIdx.x;
    int idx = bx * 256 + t;
    if (idx < 64) g_m2b[idx] = 0u;
    if (idx < NPART * NN) g_pd[idx] = 0.f;
    if (idx < WPAIRS) {
        float2 v = ((const float2*)W)[idx];
        uint32_t h = bfx2(v.x, v.y);
        g_wb_hi[idx] = h;
        g_wb_lo[idx] = bfx2(v.x - bf_lo_f(h), v.y - bf_hi_f(h));
    }
    if (bx < 64) {
        int w = t >> 5, lane = t & 31;
        int k = bx * 8 + w;
        float s1 = 0.f, s2 = 0.f;
        #pragma unroll
        for (int i = 0; i < 8; ++i) {
            int f = lane + (i << 5);
            float wv = W[k * FO + f];
            s1 += wv * a[f];
            s2 += wv * a[FO + f];
        }
        #pragma unroll
        for (int off = 16; off; off >>= 1) {
            s1 += __shfl_xor_sync(0xffffffffu, s1, off);
            s2 += __shfl_xor_sync(0xffffffffu, s2, off);
        }
        if (lane == 0) { g_wa[k] = s1; g_wa[FIN + k] = s2; }
    }
}

// ---------------------------------------------------------------------------
// k_f: f1 = x@wa1, f2 = x@wa2 (exact fp32); bucketed max of f2
// ---------------------------------------------------------------------------
__global__ void __launch_bounds__(512, 2)
k_f(const float* __restrict__ x) {
    __shared__ float wa1[FIN], wa2[FIN];
    __shared__ float fmax_s[16];
    int t = threadIdx.x, w = t >> 5, lane = t & 31;
    wa1[t] = g_wa[t];
    wa2[t] = g_wa[FIN + t];
    __syncthreads();
    int r = blockIdx.x * 16 + w;
    float s1 = 0.f, s2 = 0.f;
    #pragma unroll
    for (int i = 0; i < 16; ++i) {
        int k = lane + (i << 5);
        float xv = x[(size_t)r * FIN + k];
        s1 += xv * wa1[k];
        s2 += xv * wa2[k];
    }
    #pragma unroll
    for (int off = 16; off; off >>= 1) {
        s1 += __shfl_xor_sync(0xffffffffu, s1, off);
        s2 += __shfl_xor_sync(0xffffffffu, s2, off);
    }
    if (lane == 0) { g_f1[r] = s1; g_f2[r] = s2; fmax_s[w] = s2; }
    __syncthreads();
    if (t == 0) {
        float m = fmax_s[0];
        #pragma unroll
        for (int i = 1; i < 16; ++i) m = fmaxf(m, fmax_s[i]);
        atomicMax(&g_m2b[blockIdx.x & 63], fkey(m));
    }
}

// ---------------------------------------------------------------------------
// k_h_mma: h = x @ W, bf16 3-term, 512 threads. Epilogue: g_hb fp16 only.
// ---------------------------------------------------------------------------
#define H_AHI    0u
#define H_ALO    8192u
#define H_X(p)   (16384u + (uint32_t)(p) * 81920u)
#define H_BH(p)  (H_X(p) + 16384u)
#define H_BL(p)  (H_X(p) + 49152u)
#define SMEM_H   180224

__device__ __forceinline__ void issue_h(uint32_t sb, int p, const float* __restrict__ x,
                                        int i0, int k0, int t) {
    #pragma unroll
    for (int l = 0; l < 2; ++l) {
        int id = t + l * 512;
        int row = id >> 4, c = id & 15;
        uint32_t dst = sb + H_X(p) + row * 256 + c * 16;
        const void* src = x + (size_t)(i0 + row) * FIN + k0 + c * 4;
        CPA16(dst, src);
    }
    #pragma unroll
    for (int l = 0; l < 4; ++l) {
        int id = t + l * 512;
        int kk = id >> 5, c = id & 31;
        uint32_t dst = sb + H_BH(p) + (kk << 9) + ((c * 16) ^ ((kk & 7) << 4));
        const char* sh = (const char*)g_wb_hi + ((size_t)(k0 + kk) * FO + c * 8) * 2;
        const char* sl = (const char*)g_wb_lo + ((size_t)(k0 + kk) * FO + c * 8) * 2;
        CPA16(dst, sh);
        CPA16(dst + (H_BL(p) - H_BH(p)), sl);
    }
}

__global__ void __launch_bounds__(512, 1)
k_h_mma(const float* __restrict__ x) {
    extern __shared__ char sm[];
    uint32_t sb = smem_u32(sm);
    int t = threadIdx.x, lane = t & 31, wid = t >> 5;
    int wm = wid & 1, wn = wid >> 1;
    int i0 = blockIdx.x * 64;

    float d[2][4][4];
    #pragma unroll
    for (int m = 0; m < 2; ++m)
        #pragma unroll
        for (int n = 0; n < 4; ++n)
            #pragma unroll
            for (int c = 0; c < 4; ++c) d[m][n][c] = 0.f;

    issue_h(sb, 0, x, i0, 0, t);
    CPA_COMMIT();

    int xrow = t >> 3, xc8 = t & 7;

    for (int kc = 0; kc < 8; ++kc) {
        int s = kc & 1;
        CPA_WAITG(0);
        __syncthreads();
        if (kc + 1 < 8) { issue_h(sb, s ^ 1, x, i0, (kc + 1) * 64, t); CPA_COMMIT(); }

        {
            const float4* xp = (const float4*)(sm + H_X(s) + xrow * 256 + xc8 * 32);
            float4 v0 = xp[0], v1 = xp[1];
            uint32_t h0 = bfx2(v0.x, v0.y), h1 = bfx2(v0.z, v0.w);
            uint32_t h2 = bfx2(v1.x, v1.y), h3 = bfx2(v1.z, v1.w);
            uint32_t l0 = bfx2(v0.x - bf_lo_f(h0), v0.y - bf_hi_f(h0));
            uint32_t l1 = bfx2(v0.z - bf_lo_f(h1), v0.w - bf_hi_f(h1));
            uint32_t l2 = bfx2(v1.x - bf_lo_f(h2), v1.y - bf_hi_f(h2));
            uint32_t l3 = bfx2(v1.z - bf_lo_f(h3), v1.w - bf_hi_f(h3));
            uint32_t off = (uint32_t)(xrow * 128) + (((uint32_t)xc8 * 16) ^ ((xrow & 7) << 4));
            *(uint4*)(sm + H_AHI + off) = make_uint4(h0, h1, h2, h3);
            *(uint4*)(sm + H_ALO + off) = make_uint4(l0, l1, l2, l3);
        }
        __syncthreads();

        #pragma unroll
        for (int k0 = 0; k0 < 64; k0 += 16) {
            uint32_t ah[2][4], bh[8], bl[8];
            int arow = wm * 32 + (lane & 15);
            int acol = (k0 + ((lane >> 4) << 3)) * 2;
            int bj = k0 + (lane & 7) + ((lane & 8) ? 8 : 0);
            #pragma unroll
            for (int hB = 0; hB < 2; ++hB) {
                int f = wn * 32 + hB * 16 + ((lane & 16) ? 8 : 0);
                uint32_t off = ((uint32_t)bj << 9) + (((uint32_t)f * 2) ^ ((bj & 7) << 4));
                LDSM4T(bh[hB*4+0], bh[hB*4+1], bh[hB*4+2], bh[hB*4+3], sb + H_BH(s) + off);
                LDSM4T(bl[hB*4+0], bl[hB*4+1], bl[hB*4+2], bl[hB*4+3], sb + H_BL(s) + off);
            }
            #pragma unroll
            for (int mt = 0; mt < 2; ++mt) {
                uint32_t off = (uint32_t)((arow + mt * 16) * 128 + acol) ^ (uint32_t)((arow & 7) << 4);
                LDSM4(ah[mt][0], ah[mt][1], ah[mt][2], ah[mt][3], sb + H_AHI + off);
            }
            #pragma unroll
            for (int mt = 0; mt < 2; ++mt)
                #pragma unroll
                for (int nt = 0; nt < 4; ++nt) {
                    MMAB(d[mt][nt], ah[mt][0], ah[mt][1], ah[mt][2], ah[mt][3],
                         bh[nt*2], bh[nt*2+1]);
                    MMAB(d[mt][nt], ah[mt][0], ah[mt][1], ah[mt][2], ah[mt][3],
                         bl[nt*2], bl[nt*2+1]);
                }
            #pragma unroll
            for (int mt = 0; mt < 2; ++mt) {
                uint32_t off = (uint32_t)((arow + mt * 16) * 128 + acol) ^ (uint32_t)((arow & 7) << 4);
                LDSM4(ah[mt][0], ah[mt][1], ah[mt][2], ah[mt][3], sb + H_ALO + off);
            }
            #pragma unroll
            for (int mt = 0; mt < 2; ++mt)
                #pragma unroll
                for (int nt = 0; nt < 4; ++nt)
                    MMAB(d[mt][nt], ah[mt][0], ah[mt][1], ah[mt][2], ah[mt][3],
                         bh[nt*2], bh[nt*2+1]);
        }
    }

    #pragma unroll
    for (int mt = 0; mt < 2; ++mt) {
        int mg = i0 + wm * 32 + mt * 16 + (lane >> 2);
        #pragma unroll
        for (int nt = 0; nt < 4; ++nt) {
            int col = wn * 32 + nt * 8 + (lane & 3) * 2;
            half2 ph = __floats2half2_rn(d[mt][nt][0], d[mt][nt][1]);
            g_hb_hi[((size_t)mg * FO + col) >> 1] = *(uint32_t*)&ph;
            half2 qh = __floats2half2_rn(d[mt][nt][2], d[mt][nt][3]);
            g_hb_hi[((size_t)(mg + 8) * FO + col) >> 1] = *(uint32_t*)&qh;
        }
    }
}

// ---------------------------------------------------------------------------
// k_attn: 296 CTAs x 256 threads, 2 CTAs/SM. Job = 64 rows x 64 j.
//  adj loaded DIRECTLY from global in wcompute (no smem round-trip);
//  wcompute thread map (wr=t>>2, wq=t&3) keeps the LDG.128s coalesced.
//  Buffers: A x2 (8K) | B x2 (32K) = 80K/CTA. 1 sync/tile.
// ---------------------------------------------------------------------------
#define A_OFF(p)   ((uint32_t)(p) * 8192u)
#define B_OFF(p)   (16384u + (uint32_t)(p) * 32768u)
#define SMEM_C     81920

__device__ __forceinline__ void issue_B(uint32_t sb, int buf, int g, int t) {
    int jb = (g & 127) << 6;
    uint32_t stgB = sb + B_OFF(buf);
    #pragma unroll
    for (int l = 0; l < 8; ++l) {          // 2048 chunks of 16B
        int id = t + l * 256;
        int j = id >> 5, c = id & 31;
        uint32_t dst = stgB + (j << 9) + ((c * 16) ^ ((j & 7) << 4));
        const char* sh = (const char*)g_hb_hi + ((size_t)(jb + j) * FO + c * 8) * 2;
        CPA16(dst, sh);
    }
}

__global__ void __launch_bounds__(256, 2)
k_attn(const int* __restrict__ adj) {
    extern __shared__ char sm[];
    uint32_t sb = smem_u32(sm);

    int t    = threadIdx.x;
    int lane = t & 31, wid = t >> 5;       // wid 0..7 = N position
    int bx   = blockIdx.x;
    int st   = (bx < 104) ? bx * 56 : 5824 + (bx - 104) * 55;
    int cnt  = (bx < 104) ? 56 : 55;

    int wr = t >> 2, wq = t & 3;           // w-compute: row (0..63), j-16-group

    uint32_t mx = 0;
    #pragma unroll
    for (int i = 0; i < 64; ++i) {
        uint32_t v = g_m2b[i];
        mx = mx > v ? mx : v;
    }
    float m2 = funkey(mx);

    float d[4][4][4];
    #pragma unroll
    for (int m = 0; m < 4; ++m)
        #pragma unroll
        for (int n = 0; n < 4; ++n)
            #pragma unroll
            for (int c = 0; c < 4; ++c) d[m][n][c] = 0.f;
    float dpart = 0.f, pend[2] = {0.f, 0.f};

    auto wcompute = [&](int g, int bufA) -> float {
        char* ap = sm + A_OFF(bufA);
        int i0 = (g >> 7) << 6;
        int jb = (g & 127) << 6;
        float f1r = g_f1[i0 + wr];
        float bsh = fmaxf(f1r + m2, 0.f);
        // direct coalesced global loads (4x LDG.128 per thread)
        const int4* ar = (const int4*)(adj + (size_t)(i0 + wr) * NN + jb + wq * 16);
        int4 a0 = ar[0], a1 = ar[1], a2 = ar[2], a3 = ar[3];
        int jq = jb + wq * 16;
        float4 f20 = *(const float4*)(g_f2 + jq);
        float4 f21 = *(const float4*)(g_f2 + jq + 4);
        float4 f22 = *(const float4*)(g_f2 + jq + 8);
        float4 f23 = *(const float4*)(g_f2 + jq + 12);
        int   av[16] = {a0.x,a0.y,a0.z,a0.w, a1.x,a1.y,a1.z,a1.w,
                        a2.x,a2.y,a2.z,a2.w, a3.x,a3.y,a3.z,a3.w};
        float fv[16] = {f20.x,f20.y,f20.z,f20.w, f21.x,f21.y,f21.z,f21.w,
                        f22.x,f22.y,f22.z,f22.w, f23.x,f23.y,f23.z,f23.w};
        float w[16];
        #pragma unroll
        for (int e = 0; e < 16; ++e) {
            float sc = f1r + fv[e];
            float lr = sc > 0.f ? sc : ALPHA * sc;
            float sv = (av[e] > 0) ? lr : MASKF;
            w[e] = __expf(sv - bsh);
        }
        float dsum = 0.f;
        uint32_t hi[8];
        #pragma unroll
        for (int p = 0; p < 8; ++p) {
            half2 hp = __floats2half2_rn(w[2*p], w[2*p+1]);
            hi[p] = *(uint32_t*)&hp;
            dsum += __low2float(hp) + __high2float(hp);
        }
        uint32_t base = (uint32_t)(wr * 128 + wq * 32);
        uint32_t xo   = (uint32_t)((wr & 7) << 4);
        *(uint4*)(ap + (base ^ xo))        = make_uint4(hi[0], hi[1], hi[2], hi[3]);
        *(uint4*)(ap + ((base + 16) ^ xo)) = make_uint4(hi[4], hi[5], hi[6], hi[7]);
        return dsum;
    };

    // ---- prologue ----
    issue_B(sb, 0, st, t);
    CPA_COMMIT();
    CPA_WAITG(0);
    __syncthreads();
    pend[0] = wcompute(st, 0);

    for (int u = 0; u < cnt; ++u) {
        CPA_WAITG(0);
        __syncthreads();                   // A(u), B(u) ready

        if (u + 1 < cnt) { issue_B(sb, (u + 1) & 1, st + u + 1, t); CPA_COMMIT(); }
        if (u + 1 < cnt) pend[(u + 1) & 1] = wcompute(st + u + 1, (u + 1) & 1);

        // ---- mma(u): A[u&1], B[u&1] ----
        uint32_t stgA = sb + A_OFF(u & 1);
        uint32_t stgB = sb + B_OFF(u & 1);
        #pragma unroll
        for (int k0 = 0; k0 < KT; k0 += 16) {
            uint32_t ah[4][4], bh[8];
            int arow = lane & 15;
            int acol = (k0 + ((lane >> 4) << 3)) * 2;
            int bj = k0 + (lane & 7) + ((lane & 8) ? 8 : 0);
            #pragma unroll
            for (int hB = 0; hB < 2; ++hB) {
                int f = wid * 32 + hB * 16 + ((lane & 16) ? 8 : 0);
                uint32_t off = ((uint32_t)bj << 9) + (((uint32_t)f * 2) ^ ((bj & 7) << 4));
                LDSM4T(bh[hB*4+0], bh[hB*4+1], bh[hB*4+2], bh[hB*4+3], stgB + off);
            }
            #pragma unroll
            for (int mt = 0; mt < 4; ++mt) {
                uint32_t off = (uint32_t)((arow + mt * 16) * 128 + acol) ^ (uint32_t)((arow & 7) << 4);
                LDSM4(ah[mt][0], ah[mt][1], ah[mt][2], ah[mt][3], stgA + off);
            }
            #pragma unroll
            for (int mt = 0; mt < 4; ++mt)
                #pragma unroll
                for (int nt = 0; nt < 4; ++nt)
                    MMAH(d[mt][nt], ah[mt][0], ah[mt][1], ah[mt][2], ah[mt][3],
                         bh[nt*2], bh[nt*2+1]);
        }

        // ---- denom bookkeeping + flush on rb boundary / end ----
        dpart += pend[u & 1];
        int g = st + u;
        bool lastu = (u == cnt - 1);
        if (lastu || (((g + 1) >> 7) != (g >> 7))) {
            int rb   = g >> 7;
            int part = bx - first_cta_of(rb << 7);
            int i0   = rb << 6;
            atomicAdd(&g_pd[(size_t)part * NN + i0 + wr], dpart);
            dpart = 0.f;
            float* basep = g_pn + (size_t)part * NN * FO;
            #pragma unroll
            for (int mt = 0; mt < 4; ++mt) {
                int m = mt * 16 + (lane >> 2);
                #pragma unroll
                for (int nt = 0; nt < 4; ++nt) {
                    int col = wid * 32 + nt * 8 + (lane & 3) * 2;
                    float* dst = basep + (size_t)(i0 + m) * FO + col;
                    *(float2*)dst            = make_float2(d[mt][nt][0], d[mt][nt][1]);
                    *(float2*)(dst + 8 * FO) = make_float2(d[mt][nt][2], d[mt][nt][3]);
                    d[mt][nt][0] = 0.f; d[mt][nt][1] = 0.f;
                    d[mt][nt][2] = 0.f; d[mt][nt][3] = 0.f;
                }
            }
        }
    }
}

// ---------------------------------------------------------------------------
// k_norm: sum only the partials that have writers for this 64-row block
// ---------------------------------------------------------------------------
__global__ void k_norm(float* __restrict__ out) {
    int idx = blockIdx.x * 256 + threadIdx.x;    // float4 id
    int row = idx >> 6;
    int T0  = (row >> 6) << 7;                   // first job of this rb64
    int np  = first_cta_of(T0 + 127) - first_cta_of(T0) + 1;  // <= NPART
    float4 acc = make_float4(0.f, 0.f, 0.f, 0.f);
    float den = 0.f;
    for (int p = 0; p < np; ++p) {
        float4 v = ((const float4*)(g_pn + (size_t)p * NN * FO))[idx];
        acc.x += v.x; acc.y += v.y; acc.z += v.z; acc.w += v.w;
        den += g_pd[(size_t)p * NN + row];
    }
    float inv = 1.f / den;
    ((float4*)out)[idx] = make_float4(acc.x * inv, acc.y * inv,
                                      acc.z * inv, acc.w * inv);
}

// ---------------------------------------------------------------------------
extern "C" void kernel_launch(void* const* d_in, const int* in_sizes, int n_in,
                              void* d_out, int out_size) {
    const float* x   = (const float*)d_in[0];
    const int*   adj = (const int*)  d_in[1];
    const float* W   = (const float*)d_in[2];
    const float* a   = (const float*)d_in[3];
    float*       out = (float*)d_out;

    cudaFuncSetAttribute(k_h_mma, cudaFuncAttributeMaxDynamicSharedMemorySize, SMEM_H);
    cudaFuncSetAttribute(k_attn,  cudaFuncAttributeMaxDynamicSharedMemorySize, SMEM_C);

    k_conv <<<256, 256>>>(W, a);
    k_f    <<<512, 512>>>(x);
    k_h_mma<<<128, 512, SMEM_H>>>(x);
    k_attn <<<296, 256, SMEM_C>>>(adj);
    k_norm <<<2048, 256>>>(out);
}

// round 16
// speedup vs baseline: 1.0461x; 1.0461x over previous
#include <cuda_runtime.h>
#include <cuda_bf16.h>
#include <cuda_fp16.h>
#include <cstdint>

#define NN   8192
#define FIN  512
#define FO   256
#define ALPHA 0.2f
#define MASKF 9e-15f

#define KT     64
#define NPART  4

#define WPAIRS (FIN*FO/2)

// Scratch (device globals — no allocation allowed)
__device__ __align__(16) uint32_t g_wb_hi[WPAIRS];
__device__ __align__(16) uint32_t g_wb_lo[WPAIRS];
__device__ __align__(16) uint32_t g_hb_hi[NN * FO / 2];   // fp16x2 [i][f]
__device__ __align__(16) float    g_pn   [NPART * NN * FO];
__device__ __align__(16) float    g_pd   [NPART * NN];
__device__ __align__(16) float    g_f1   [NN];
__device__ __align__(16) float    g_f2   [NN];
__device__ __align__(16) float    g_e1   [NN];             // exp(f2)
__device__ __align__(16) float    g_e2   [NN];             // exp(0.2*f2)
__device__ __align__(16) float    g_wa   [2 * FIN];        // W@a1, W@a2
__device__ uint32_t g_m2b[64];                             // bucketed max f2 (fkey)

// ---------------------------------------------------------------------------
// helpers
// ---------------------------------------------------------------------------
__device__ __forceinline__ uint32_t smem_u32(const void* p) {
    uint32_t a;
    asm("{ .reg .u64 t; cvta.to.shared.u64 t, %1; cvt.u32.u64 %0, t; }"
        : "=r"(a) : "l"(p));
    return a;
}
__device__ __forceinline__ uint32_t bfx2(float lo, float hi) {
    uint32_t r;
    asm("cvt.rn.bf16x2.f32 %0, %1, %2;" : "=r"(r) : "f"(hi), "f"(lo));
    return r;
}
__device__ __forceinline__ float bf_lo_f(uint32_t p) { return __uint_as_float(p << 16); }
__device__ __forceinline__ float bf_hi_f(uint32_t p) { return __uint_as_float(p & 0xFFFF0000u); }

__device__ __forceinline__ uint32_t fkey(float f) {
    uint32_t b = __float_as_uint(f);
    return (b & 0x80000000u) ? ~b : (b | 0x80000000u);
}
__device__ __forceinline__ float funkey(uint32_t k) {
    uint32_t b = (k & 0x80000000u) ? (k & 0x7FFFFFFFu) : ~k;
    return __uint_as_float(b);
}

// CTA whose job range contains job T  (16384 jobs = 104 CTAs x56 + 192 x55)
__device__ __forceinline__ int first_cta_of(int T) {
    return (T < 5824) ? (T / 56) : (104 + (T - 5824) / 55);
}

#define CPA16(dst, src) \
    asm volatile("cp.async.cg.shared.global [%0], [%1], 16;" :: "r"(dst), "l"(src) : "memory")
#define CPA_COMMIT() asm volatile("cp.async.commit_group;" ::: "memory")
#define CPA_WAITG(n) asm volatile("cp.async.wait_group %0;" :: "n"(n) : "memory")

#define LDSM4(R0,R1,R2,R3,addr) \
    asm volatile("ldmatrix.sync.aligned.m8n8.x4.shared.b16 {%0,%1,%2,%3}, [%4];" \
        : "=r"(R0), "=r"(R1), "=r"(R2), "=r"(R3) : "r"(addr))
#define LDSM4T(R0,R1,R2,R3,addr) \
    asm volatile("ldmatrix.sync.aligned.m8n8.x4.trans.shared.b16 {%0,%1,%2,%3}, [%4];" \
        : "=r"(R0), "=r"(R1), "=r"(R2), "=r"(R3) : "r"(addr))

#define MMAB(D, a0,a1,a2,a3, b0,b1) \
    asm volatile("mma.sync.aligned.m16n8k16.row.col.f32.bf16.bf16.f32 " \
        "{%0,%1,%2,%3}, {%4,%5,%6,%7}, {%8,%9}, {%0,%1,%2,%3};" \
        : "+f"((D)[0]), "+f"((D)[1]), "+f"((D)[2]), "+f"((D)[3]) \
        : "r"(a0), "r"(a1), "r"(a2), "r"(a3), "r"(b0), "r"(b1))

#define MMAH(D, a0,a1,a2,a3, b0,b1) \
    asm volatile("mma.sync.aligned.m16n8k16.row.col.f32.f16.f16.f32 " \
        "{%0,%1,%2,%3}, {%4,%5,%6,%7}, {%8,%9}, {%0,%1,%2,%3};" \
        : "+f"((D)[0]), "+f"((D)[1]), "+f"((D)[2]), "+f"((D)[3]) \
        : "r"(a0), "r"(a1), "r"(a2), "r"(a3), "r"(b0), "r"(b1))

// ---------------------------------------------------------------------------
// k_conv: split W to bf16 hi/lo; compute wa = W@a1 / W@a2; zero pd/m2b
// ---------------------------------------------------------------------------
__global__ void k_conv(const float* __restrict__ W, const float* __restrict__ a) {
    int t = threadIdx.x, bx = blockIdx.x;
    int idx = bx * 256 + t;
    if (idx < 64) g_m2b[idx] = 0u;
    if (idx < NPART * NN) g_pd[idx] = 0.f;
    if (idx < WPAIRS) {
        float2 v = ((const float2*)W)[idx];
        uint32_t h = bfx2(v.x, v.y);
        g_wb_hi[idx] = h;
        g_wb_lo[idx] = bfx2(v.x - bf_lo_f(h), v.y - bf_hi_f(h));
    }
    if (bx < 64) {
        int w = t >> 5, lane = t & 31;
        int k = bx * 8 + w;
        float s1 = 0.f, s2 = 0.f;
        #pragma unroll
        for (int i = 0; i < 8; ++i) {
            int f = lane + (i << 5);
            float wv = W[k * FO + f];
            s1 += wv * a[f];
            s2 += wv * a[FO + f];
        }
        #pragma unroll
        for (int off = 16; off; off >>= 1) {
            s1 += __shfl_xor_sync(0xffffffffu, s1, off);
            s2 += __shfl_xor_sync(0xffffffffu, s2, off);
        }
        if (lane == 0) { g_wa[k] = s1; g_wa[FIN + k] = s2; }
    }
}

// ---------------------------------------------------------------------------
// k_f: f1 = x@wa1, f2 = x@wa2 (exact fp32); e1=exp(f2), e2=exp(0.2 f2);
//      bucketed max of f2
// ---------------------------------------------------------------------------
__global__ void __launch_bounds__(512, 2)
k_f(const float* __restrict__ x) {
    __shared__ float wa1[FIN], wa2[FIN];
    __shared__ float fmax_s[16];
    int t = threadIdx.x, w = t >> 5, lane = t & 31;
    wa1[t] = g_wa[t];
    wa2[t] = g_wa[FIN + t];
    __syncthreads();
    int r = blockIdx.x * 16 + w;
    float s1 = 0.f, s2 = 0.f;
    #pragma unroll
    for (int i = 0; i < 16; ++i) {
        int k = lane + (i << 5);
        float xv = x[(size_t)r * FIN + k];
        s1 += xv * wa1[k];
        s2 += xv * wa2[k];
    }
    #pragma unroll
    for (int off = 16; off; off >>= 1) {
        s1 += __shfl_xor_sync(0xffffffffu, s1, off);
        s2 += __shfl_xor_sync(0xffffffffu, s2, off);
    }
    if (lane == 0) {
        g_f1[r] = s1;
        g_f2[r] = s2;
        g_e1[r] = __expf(s2);
        g_e2[r] = __expf(ALPHA * s2);
        fmax_s[w] = s2;
    }
    __syncthreads();
    if (t == 0) {
        float m = fmax_s[0];
        #pragma unroll
        for (int i = 1; i < 16; ++i) m = fmaxf(m, fmax_s[i]);
        atomicMax(&g_m2b[blockIdx.x & 63], fkey(m));
    }
}

// ---------------------------------------------------------------------------
// k_h_mma: h = x @ W, bf16 3-term, 512 threads. Epilogue: g_hb fp16 only.
// ---------------------------------------------------------------------------
#define H_AHI    0u
#define H_ALO    8192u
#define H_X(p)   (16384u + (uint32_t)(p) * 81920u)
#define H_BH(p)  (H_X(p) + 16384u)
#define H_BL(p)  (H_X(p) + 49152u)
#define SMEM_H   180224

__device__ __forceinline__ void issue_h(uint32_t sb, int p, const float* __restrict__ x,
                                        int i0, int k0, int t) {
    #pragma unroll
    for (int l = 0; l < 2; ++l) {
        int id = t + l * 512;
        int row = id >> 4, c = id & 15;
        uint32_t dst = sb + H_X(p) + row * 256 + c * 16;
        const void* src = x + (size_t)(i0 + row) * FIN + k0 + c * 4;
        CPA16(dst, src);
    }
    #pragma unroll
    for (int l = 0; l < 4; ++l) {
        int id = t + l * 512;
        int kk = id >> 5, c = id & 31;
        uint32_t dst = sb + H_BH(p) + (kk << 9) + ((c * 16) ^ ((kk & 7) << 4));
        const char* sh = (const char*)g_wb_hi + ((size_t)(k0 + kk) * FO + c * 8) * 2;
        const char* sl = (const char*)g_wb_lo + ((size_t)(k0 + kk) * FO + c * 8) * 2;
        CPA16(dst, sh);
        CPA16(dst + (H_BL(p) - H_BH(p)), sl);
    }
}

__global__ void __launch_bounds__(512, 1)
k_h_mma(const float* __restrict__ x) {
    extern __shared__ char sm[];
    uint32_t sb = smem_u32(sm);
    int t = threadIdx.x, lane = t & 31, wid = t >> 5;
    int wm = wid & 1, wn = wid >> 1;
    int i0 = blockIdx.x * 64;

    float d[2][4][4];
    #pragma unroll
    for (int m = 0; m < 2; ++m)
        #pragma unroll
        for (int n = 0; n < 4; ++n)
            #pragma unroll
            for (int c = 0; c < 4; ++c) d[m][n][c] = 0.f;

    issue_h(sb, 0, x, i0, 0, t);
    CPA_COMMIT();

    int xrow = t >> 3, xc8 = t & 7;

    for (int kc = 0; kc < 8; ++kc) {
        int s = kc & 1;
        CPA_WAITG(0);
        __syncthreads();
        if (kc + 1 < 8) { issue_h(sb, s ^ 1, x, i0, (kc + 1) * 64, t); CPA_COMMIT(); }

        {
            const float4* xp = (const float4*)(sm + H_X(s) + xrow * 256 + xc8 * 32);
            float4 v0 = xp[0], v1 = xp[1];
            uint32_t h0 = bfx2(v0.x, v0.y), h1 = bfx2(v0.z, v0.w);
            uint32_t h2 = bfx2(v1.x, v1.y), h3 = bfx2(v1.z, v1.w);
            uint32_t l0 = bfx2(v0.x - bf_lo_f(h0), v0.y - bf_hi_f(h0));
            uint32_t l1 = bfx2(v0.z - bf_lo_f(h1), v0.w - bf_hi_f(h1));
            uint32_t l2 = bfx2(v1.x - bf_lo_f(h2), v1.y - bf_hi_f(h2));
            uint32_t l3 = bfx2(v1.z - bf_lo_f(h3), v1.w - bf_hi_f(h3));
            uint32_t off = (uint32_t)(xrow * 128) + (((uint32_t)xc8 * 16) ^ ((xrow & 7) << 4));
            *(uint4*)(sm + H_AHI + off) = make_uint4(h0, h1, h2, h3);
            *(uint4*)(sm + H_ALO + off) = make_uint4(l0, l1, l2, l3);
        }
        __syncthreads();

        #pragma unroll
        for (int k0 = 0; k0 < 64; k0 += 16) {
            uint32_t ah[2][4], bh[8], bl[8];
            int arow = wm * 32 + (lane & 15);
            int acol = (k0 + ((lane >> 4) << 3)) * 2;
            int bj = k0 + (lane & 7) + ((lane & 8) ? 8 : 0);
            #pragma unroll
            for (int hB = 0; hB < 2; ++hB) {
                int f = wn * 32 + hB * 16 + ((lane & 16) ? 8 : 0);
                uint32_t off = ((uint32_t)bj << 9) + (((uint32_t)f * 2) ^ ((bj & 7) << 4));
                LDSM4T(bh[hB*4+0], bh[hB*4+1], bh[hB*4+2], bh[hB*4+3], sb + H_BH(s) + off);
                LDSM4T(bl[hB*4+0], bl[hB*4+1], bl[hB*4+2], bl[hB*4+3], sb + H_BL(s) + off);
            }
            #pragma unroll
            for (int mt = 0; mt < 2; ++mt) {
                uint32_t off = (uint32_t)((arow + mt * 16) * 128 + acol) ^ (uint32_t)((arow & 7) << 4);
                LDSM4(ah[mt][0], ah[mt][1], ah[mt][2], ah[mt][3], sb + H_AHI + off);
            }
            #pragma unroll
            for (int mt = 0; mt < 2; ++mt)
                #pragma unroll
                for (int nt = 0; nt < 4; ++nt) {
                    MMAB(d[mt][nt], ah[mt][0], ah[mt][1], ah[mt][2], ah[mt][3],
                         bh[nt*2], bh[nt*2+1]);
                    MMAB(d[mt][nt], ah[mt][0], ah[mt][1], ah[mt][2], ah[mt][3],
                         bl[nt*2], bl[nt*2+1]);
                }
            #pragma unroll
            for (int mt = 0; mt < 2; ++mt) {
                uint32_t off = (uint32_t)((arow + mt * 16) * 128 + acol) ^ (uint32_t)((arow & 7) << 4);
                LDSM4(ah[mt][0], ah[mt][1], ah[mt][2], ah[mt][3], sb + H_ALO + off);
            }
            #pragma unroll
            for (int mt = 0; mt < 2; ++mt)
                #pragma unroll
                for (int nt = 0; nt < 4; ++nt)
                    MMAB(d[mt][nt], ah[mt][0], ah[mt][1], ah[mt][2], ah[mt][3],
                         bh[nt*2], bh[nt*2+1]);
        }
    }

    #pragma unroll
    for (int mt = 0; mt < 2; ++mt) {
        int mg = i0 + wm * 32 + mt * 16 + (lane >> 2);
        #pragma unroll
        for (int nt = 0; nt < 4; ++nt) {
            int col = wn * 32 + nt * 8 + (lane & 3) * 2;
            half2 ph = __floats2half2_rn(d[mt][nt][0], d[mt][nt][1]);
            g_hb_hi[((size_t)mg * FO + col) >> 1] = *(uint32_t*)&ph;
            half2 qh = __floats2half2_rn(d[mt][nt][2], d[mt][nt][3]);
            g_hb_hi[((size_t)(mg + 8) * FO + col) >> 1] = *(uint32_t*)&qh;
        }
    }
}

// ---------------------------------------------------------------------------
// k_attn: 296 CTAs x 256 threads, 2 CTAs/SM. Job = 64 rows x 64 j.
//  adj via cp.async smem staging (R14). wcompute uses factored exp:
//  w = adj ? (e1>T1 ? C1*e1 : C2*e2) : enb  — 4 MUFU/call instead of 16.
//  Buffers: A x2 (8K) | B x2 (32K) | adj x2 (16K, 256B swizzled rows).
// ---------------------------------------------------------------------------
#define A_OFF(p)   ((uint32_t)(p) * 8192u)
#define B_OFF(p)   (16384u + (uint32_t)(p) * 32768u)
#define ADJ_OFF(p) (81920u + (uint32_t)(p) * 16384u)
#define SMEM_C     114688

__device__ __forceinline__ void issue_B(uint32_t sb, int buf, int g, int t) {
    int jb = (g & 127) << 6;
    uint32_t stgB = sb + B_OFF(buf);
    #pragma unroll
    for (int l = 0; l < 8; ++l) {          // 2048 chunks of 16B
        int id = t + l * 256;
        int j = id >> 5, c = id & 31;
        uint32_t dst = stgB + (j << 9) + ((c * 16) ^ ((j & 7) << 4));
        const char* sh = (const char*)g_hb_hi + ((size_t)(jb + j) * FO + c * 8) * 2;
        CPA16(dst, sh);
    }
}
__device__ __forceinline__ void issue_adj(uint32_t sb, int buf,
                                          const int* __restrict__ adj, int g, int t) {
    int i0 = (g >> 7) << 6;
    int jb = (g & 127) << 6;
    uint32_t stgJ = sb + ADJ_OFF(buf);
    #pragma unroll
    for (int l = 0; l < 4; ++l) {          // 1024 chunks, 256B swizzled rows
        int id = t + l * 256;
        int r = id >> 4, c = id & 15;
        uint32_t dst = stgJ + r * 256 + ((c * 16) ^ ((r & 15) << 4));
        const void* src = adj + (size_t)(i0 + r) * NN + jb + c * 4;
        CPA16(dst, src);
    }
}

__global__ void __launch_bounds__(256, 2)
k_attn(const int* __restrict__ adj) {
    extern __shared__ char sm[];
    uint32_t sb = smem_u32(sm);

    int t    = threadIdx.x;
    int lane = t & 31, wid = t >> 5;       // wid 0..7 = N position
    int bx   = blockIdx.x;
    int st   = (bx < 104) ? bx * 56 : 5824 + (bx - 104) * 55;
    int cnt  = (bx < 104) ? 56 : 55;

    int wr = t & 63, wq = t >> 6;          // w-compute: row (0..63), j-16-group

    uint32_t mx = 0;
    #pragma unroll
    for (int i = 0; i < 64; ++i) {
        uint32_t v = g_m2b[i];
        mx = mx > v ? mx : v;
    }
    float m2 = funkey(mx);

    float d[4][4][4];
    #pragma unroll
    for (int m = 0; m < 4; ++m)
        #pragma unroll
        for (int n = 0; n < 4; ++n)
            #pragma unroll
            for (int c = 0; c < 4; ++c) d[m][n][c] = 0.f;
    float dpart = 0.f, pend[2] = {0.f, 0.f};

    auto wcompute = [&](int g, int bufA) -> float {
        uint32_t jro = (uint32_t)(wr * 256);
        uint32_t jxo = (uint32_t)((wr & 15) << 4);
        const char* adjb = sm + ADJ_OFF(bufA);
        char*       ap   = sm + A_OFF(bufA);
        float f1r = g_f1[((g >> 7) << 6) + wr];
        float bsh = fmaxf(f1r + m2, 0.f);
        float C1  = __expf(f1r - bsh);
        float C2  = __expf(ALPHA * f1r - bsh);
        float T1  = __expf(-f1r);
        float enb = __expf(MASKF - bsh);
        int4 a0 = *(const int4*)(adjb + jro + (((wq * 64) +  0) ^ jxo));
        int4 a1 = *(const int4*)(adjb + jro + (((wq * 64) + 16) ^ jxo));
        int4 a2 = *(const int4*)(adjb + jro + (((wq * 64) + 32) ^ jxo));
        int4 a3 = *(const int4*)(adjb + jro + (((wq * 64) + 48) ^ jxo));
        int jq = ((g & 127) << 6) + wq * 16;
        int av[16] = {a0.x,a0.y,a0.z,a0.w, a1.x,a1.y,a1.z,a1.w,
                      a2.x,a2.y,a2.z,a2.w, a3.x,a3.y,a3.z,a3.w};
        float dsum = 0.f;
        uint32_t hi[8];
        #pragma unroll
        for (int p = 0; p < 4; ++p) {
            float4 e1q = *(const float4*)(g_e1 + jq + 4 * p);
            float4 e2q = *(const float4*)(g_e2 + jq + 4 * p);
            float w0 = (av[4*p+0] > 0) ? (e1q.x > T1 ? C1 * e1q.x : C2 * e2q.x) : enb;
            float w1 = (av[4*p+1] > 0) ? (e1q.y > T1 ? C1 * e1q.y : C2 * e2q.y) : enb;
            float w2 = (av[4*p+2] > 0) ? (e1q.z > T1 ? C1 * e1q.z : C2 * e2q.z) : enb;
            float w3 = (av[4*p+3] > 0) ? (e1q.w > T1 ? C1 * e1q.w : C2 * e2q.w) : enb;
            half2 h0 = __floats2half2_rn(w0, w1);
            half2 h1 = __floats2half2_rn(w2, w3);
            hi[2*p]   = *(uint32_t*)&h0;
            hi[2*p+1] = *(uint32_t*)&h1;
            dsum += __low2float(h0) + __high2float(h0)
                  + __low2float(h1) + __high2float(h1);
        }
        uint32_t base = (uint32_t)(wr * 128 + wq * 32);
        uint32_t xo   = (uint32_t)((wr & 7) << 4);
        *(uint4*)(ap + (base ^ xo))        = make_uint4(hi[0], hi[1], hi[2], hi[3]);
        *(uint4*)(ap + ((base + 16) ^ xo)) = make_uint4(hi[4], hi[5], hi[6], hi[7]);
        return dsum;
    };

    // ---- prologue ----
    issue_B(sb, 0, st, t);
    issue_adj(sb, 0, adj, st, t);
    if (cnt > 1) issue_adj(sb, 1, adj, st + 1, t);
    CPA_COMMIT();
    CPA_WAITG(0);
    __syncthreads();
    pend[0] = wcompute(st, 0);

    for (int u = 0; u < cnt; ++u) {
        CPA_WAITG(0);
        __syncthreads();                   // A(u), B(u), adj(u+1) ready

        if (u + 1 < cnt) issue_B(sb, (u + 1) & 1, st + u + 1, t);
        if (u + 2 < cnt) issue_adj(sb, u & 1, adj, st + u + 2, t);
        CPA_COMMIT();
        if (u + 1 < cnt) pend[(u + 1) & 1] = wcompute(st + u + 1, (u + 1) & 1);

        // ---- mma(u): A[u&1], B[u&1] ----
        uint32_t stgA = sb + A_OFF(u & 1);
        uint32_t stgB = sb + B_OFF(u & 1);
        #pragma unroll
        for (int k0 = 0; k0 < KT; k0 += 16) {
            uint32_t ah[4][4], bh[8];
            int arow = lane & 15;
            int acol = (k0 + ((lane >> 4) << 3)) * 2;
            int bj = k0 + (lane & 7) + ((lane & 8) ? 8 : 0);
            #pragma unroll
            for (int hB = 0; hB < 2; ++hB) {
                int f = wid * 32 + hB * 16 + ((lane & 16) ? 8 : 0);
                uint32_t off = ((uint32_t)bj << 9) + (((uint32_t)f * 2) ^ ((bj & 7) << 4));
                LDSM4T(bh[hB*4+0], bh[hB*4+1], bh[hB*4+2], bh[hB*4+3], stgB + off);
            }
            #pragma unroll
            for (int mt = 0; mt < 4; ++mt) {
                uint32_t off = (uint32_t)((arow + mt * 16) * 128 + acol) ^ (uint32_t)((arow & 7) << 4);
                LDSM4(ah[mt][0], ah[mt][1], ah[mt][2], ah[mt][3], stgA + off);
            }
            #pragma unroll
            for (int mt = 0; mt < 4; ++mt)
                #pragma unroll
                for (int nt = 0; nt < 4; ++nt)
                    MMAH(d[mt][nt], ah[mt][0], ah[mt][1], ah[mt][2], ah[mt][3],
                         bh[nt*2], bh[nt*2+1]);
        }

        // ---- denom bookkeeping + flush on rb boundary / end ----
        dpart += pend[u & 1];
        int g = st + u;
        bool lastu = (u == cnt - 1);
        if (lastu || (((g + 1) >> 7) != (g >> 7))) {
            int rb   = g >> 7;
            int part = bx - first_cta_of(rb << 7);
            int i0   = rb << 6;
            atomicAdd(&g_pd[(size_t)part * NN + i0 + wr], dpart);
            dpart = 0.f;
            float* basep = g_pn + (size_t)part * NN * FO;
            #pragma unroll
            for (int mt = 0; mt < 4; ++mt) {
                int m = mt * 16 + (lane >> 2);
                #pragma unroll
                for (int nt = 0; nt < 4; ++nt) {
                    int col = wid * 32 + nt * 8 + (lane & 3) * 2;
                    float* dst = basep + (size_t)(i0 + m) * FO + col;
                    *(float2*)dst            = make_float2(d[mt][nt][0], d[mt][nt][1]);
                    *(float2*)(dst + 8 * FO) = make_float2(d[mt][nt][2], d[mt][nt][3]);
                    d[mt][nt][0] = 0.f; d[mt][nt][1] = 0.f;
                    d[mt][nt][2] = 0.f; d[mt][nt][3] = 0.f;
                }
            }
        }
    }
}

// ---------------------------------------------------------------------------
// k_norm: sum only the partials that have writers for this 64-row block
// ---------------------------------------------------------------------------
__global__ void k_norm(float* __restrict__ out) {
    int idx = blockIdx.x * 256 + threadIdx.x;    // float4 id
    int row = idx >> 6;
    int T0  = (row >> 6) << 7;                   // first job of this rb64
    int np  = first_cta_of(T0 + 127) - first_cta_of(T0) + 1;  // <= NPART
    float4 acc = make_float4(0.f, 0.f, 0.f, 0.f);
    float den = 0.f;
    for (int p = 0; p < np; ++p) {
        float4 v = ((const float4*)(g_pn + (size_t)p * NN * FO))[idx];
        acc.x += v.x; acc.y += v.y; acc.z += v.z; acc.w += v.w;
        den += g_pd[(size_t)p * NN + row];
    }
    float inv = 1.f / den;
    ((float4*)out)[idx] = make_float4(acc.x * inv, acc.y * inv,
                                      acc.z * inv, acc.w * inv);
}

// ---------------------------------------------------------------------------
extern "C" void kernel_launch(void* const* d_in, const int* in_sizes, int n_in,
                              void* d_out, int out_size) {
    const float* x   = (const float*)d_in[0];
    const int*   adj = (const int*)  d_in[1];
    const float* W   = (const float*)d_in[2];
    const float* a   = (const float*)d_in[3];
    float*       out = (float*)d_out;

    cudaFuncSetAttribute(k_h_mma, cudaFuncAttributeMaxDynamicSharedMemorySize, SMEM_H);
    cudaFuncSetAttribute(k_attn,  cudaFuncAttributeMaxDynamicSharedMemorySize, SMEM_C);

    k_conv <<<256, 256>>>(W, a);
    k_f    <<<512, 512>>>(x);
    k_h_mma<<<128, 512, SMEM_H>>>(x);
    k_attn <<<296, 256, SMEM_C>>>(adj);
    k_norm <<<2048, 256>>>(out);
}

// round 17
// speedup vs baseline: 1.0509x; 1.0046x over previous
#include <cuda_runtime.h>
#include <cuda_bf16.h>
#include <cuda_fp16.h>
#include <cstdint>

#define NN   8192
#define FIN  512
#define FO   256
#define ALPHA 0.2f
#define MASKF 9e-15f

#define KT     64
#define NPART  4

#define WPAIRS (FIN*FO/2)

// Scratch (device globals — no allocation allowed)
__device__ __align__(16) uint32_t g_wb_hi[WPAIRS];
__device__ __align__(16) uint32_t g_wb_lo[WPAIRS];
__device__ __align__(16) uint32_t g_hb_hi[NN * FO / 2];   // fp16x2 [i][f]
__device__ __align__(16) float    g_pn   [NPART * NN * FO];
__device__ __align__(16) float    g_pd   [NPART * NN];
__device__ __align__(16) float    g_f1   [NN];
__device__ __align__(16) float    g_f2   [NN];
__device__ __align__(16) float    g_e1   [NN];             // exp(f2)
__device__ __align__(16) float    g_e2   [NN];             // exp(0.2*f2)
__device__ __align__(16) float    g_wa   [2 * FIN];        // W@a1, W@a2
__device__ uint32_t g_m2b[64];                             // bucketed max f2 (fkey)

// ---------------------------------------------------------------------------
// helpers
// ---------------------------------------------------------------------------
__device__ __forceinline__ uint32_t smem_u32(const void* p) {
    uint32_t a;
    asm("{ .reg .u64 t; cvta.to.shared.u64 t, %1; cvt.u32.u64 %0, t; }"
        : "=r"(a) : "l"(p));
    return a;
}
__device__ __forceinline__ uint32_t bfx2(float lo, float hi) {
    uint32_t r;
    asm("cvt.rn.bf16x2.f32 %0, %1, %2;" : "=r"(r) : "f"(hi), "f"(lo));
    return r;
}
__device__ __forceinline__ float bf_lo_f(uint32_t p) { return __uint_as_float(p << 16); }
__device__ __forceinline__ float bf_hi_f(uint32_t p) { return __uint_as_float(p & 0xFFFF0000u); }

__device__ __forceinline__ uint32_t fkey(float f) {
    uint32_t b = __float_as_uint(f);
    return (b & 0x80000000u) ? ~b : (b | 0x80000000u);
}
__device__ __forceinline__ float funkey(uint32_t k) {
    uint32_t b = (k & 0x80000000u) ? (k & 0x7FFFFFFFu) : ~k;
    return __uint_as_float(b);
}

// CTA whose job range contains job T  (16384 jobs = 104 CTAs x56 + 192 x55)
__device__ __forceinline__ int first_cta_of(int T) {
    return (T < 5824) ? (T / 56) : (104 + (T - 5824) / 55);
}

#define CPA16(dst, src) \
    asm volatile("cp.async.cg.shared.global [%0], [%1], 16;" :: "r"(dst), "l"(src) : "memory")
#define CPA_COMMIT() asm volatile("cp.async.commit_group;" ::: "memory")
#define CPA_WAITG(n) asm volatile("cp.async.wait_group %0;" :: "n"(n) : "memory")

#define LDSM4(R0,R1,R2,R3,addr) \
    asm volatile("ldmatrix.sync.aligned.m8n8.x4.shared.b16 {%0,%1,%2,%3}, [%4];" \
        : "=r"(R0), "=r"(R1), "=r"(R2), "=r"(R3) : "r"(addr))
#define LDSM4T(R0,R1,R2,R3,addr) \
    asm volatile("ldmatrix.sync.aligned.m8n8.x4.trans.shared.b16 {%0,%1,%2,%3}, [%4];" \
        : "=r"(R0), "=r"(R1), "=r"(R2), "=r"(R3) : "r"(addr))

#define MMAB(D, a0,a1,a2,a3, b0,b1) \
    asm volatile("mma.sync.aligned.m16n8k16.row.col.f32.bf16.bf16.f32 " \
        "{%0,%1,%2,%3}, {%4,%5,%6,%7}, {%8,%9}, {%0,%1,%2,%3};" \
        : "+f"((D)[0]), "+f"((D)[1]), "+f"((D)[2]), "+f"((D)[3]) \
        : "r"(a0), "r"(a1), "r"(a2), "r"(a3), "r"(b0), "r"(b1))

#define MMAH(D, a0,a1,a2,a3, b0,b1) \
    asm volatile("mma.sync.aligned.m16n8k16.row.col.f32.f16.f16.f32 " \
        "{%0,%1,%2,%3}, {%4,%5,%6,%7}, {%8,%9}, {%0,%1,%2,%3};" \
        : "+f"((D)[0]), "+f"((D)[1]), "+f"((D)[2]), "+f"((D)[3]) \
        : "r"(a0), "r"(a1), "r"(a2), "r"(a3), "r"(b0), "r"(b1))

// ---------------------------------------------------------------------------
// k_conv: split W to bf16 hi/lo; compute wa = W@a1 / W@a2; zero pd/m2b
// ---------------------------------------------------------------------------
__global__ void k_conv(const float* __restrict__ W, const float* __restrict__ a) {
    int t = threadIdx.x, bx = blockIdx.x;
    int idx = bx * 256 + t;
    if (idx < 64) g_m2b[idx] = 0u;
    if (idx < NPART * NN) g_pd[idx] = 0.f;
    if (idx < WPAIRS) {
        float2 v = ((const float2*)W)[idx];
        uint32_t h = bfx2(v.x, v.y);
        g_wb_hi[idx] = h;
        g_wb_lo[idx] = bfx2(v.x - bf_lo_f(h), v.y - bf_hi_f(h));
    }
    if (bx < 64) {
        int w = t >> 5, lane = t & 31;
        int k = bx * 8 + w;
        float s1 = 0.f, s2 = 0.f;
        #pragma unroll
        for (int i = 0; i < 8; ++i) {
            int f = lane + (i << 5);
            float wv = W[k * FO + f];
            s1 += wv * a[f];
            s2 += wv * a[FO + f];
        }
        #pragma unroll
        for (int off = 16; off; off >>= 1) {
            s1 += __shfl_xor_sync(0xffffffffu, s1, off);
            s2 += __shfl_xor_sync(0xffffffffu, s2, off);
        }
        if (lane == 0) { g_wa[k] = s1; g_wa[FIN + k] = s2; }
    }
}

// ---------------------------------------------------------------------------
// k_h_mma: h = x @ W, bf16 3-term, 512 threads. Epilogue: g_hb fp16,
//  plus folded f1/f2/e1/e2/max (k_f deleted): per-thread dot of the 8 x
//  values already in hand against smem wa, 3-level shfl reduce per row.
// ---------------------------------------------------------------------------
#define H_AHI    0u
#define H_ALO    8192u
#define H_X(p)   (16384u + (uint32_t)(p) * 81920u)
#define H_BH(p)  (H_X(p) + 16384u)
#define H_BL(p)  (H_X(p) + 49152u)
#define SMEM_H   180224

__device__ __forceinline__ void issue_h(uint32_t sb, int p, const float* __restrict__ x,
                                        int i0, int k0, int t) {
    #pragma unroll
    for (int l = 0; l < 2; ++l) {
        int id = t + l * 512;
        int row = id >> 4, c = id & 15;
        uint32_t dst = sb + H_X(p) + row * 256 + c * 16;
        const void* src = x + (size_t)(i0 + row) * FIN + k0 + c * 4;
        CPA16(dst, src);
    }
    #pragma unroll
    for (int l = 0; l < 4; ++l) {
        int id = t + l * 512;
        int kk = id >> 5, c = id & 31;
        uint32_t dst = sb + H_BH(p) + (kk << 9) + ((c * 16) ^ ((kk & 7) << 4));
        const char* sh = (const char*)g_wb_hi + ((size_t)(k0 + kk) * FO + c * 8) * 2;
        const char* sl = (const char*)g_wb_lo + ((size_t)(k0 + kk) * FO + c * 8) * 2;
        CPA16(dst, sh);
        CPA16(dst + (H_BL(p) - H_BH(p)), sl);
    }
}

__global__ void __launch_bounds__(512, 1)
k_h_mma(const float* __restrict__ x) {
    extern __shared__ char sm[];
    __shared__ float wa1_s[FIN], wa2_s[FIN];
    __shared__ uint32_t mx_s;
    uint32_t sb = smem_u32(sm);
    int t = threadIdx.x, lane = t & 31, wid = t >> 5;
    int wm = wid & 1, wn = wid >> 1;
    int i0 = blockIdx.x * 64;

    wa1_s[t] = g_wa[t];
    wa2_s[t] = g_wa[FIN + t];
    if (t == 0) mx_s = 0u;

    float d[2][4][4];
    #pragma unroll
    for (int m = 0; m < 2; ++m)
        #pragma unroll
        for (int n = 0; n < 4; ++n)
            #pragma unroll
            for (int c = 0; c < 4; ++c) d[m][n][c] = 0.f;
    float s1 = 0.f, s2 = 0.f;

    issue_h(sb, 0, x, i0, 0, t);
    CPA_COMMIT();

    int xrow = t >> 3, xc8 = t & 7;

    for (int kc = 0; kc < 8; ++kc) {
        int s = kc & 1;
        CPA_WAITG(0);
        __syncthreads();
        if (kc + 1 < 8) { issue_h(sb, s ^ 1, x, i0, (kc + 1) * 64, t); CPA_COMMIT(); }

        {
            const float4* xp = (const float4*)(sm + H_X(s) + xrow * 256 + xc8 * 32);
            float4 v0 = xp[0], v1 = xp[1];
            // folded f1/f2 partial dot (8 terms per kc)
            int kb = kc * 64 + xc8 * 8;
            s1 += v0.x * wa1_s[kb]     + v0.y * wa1_s[kb + 1]
                + v0.z * wa1_s[kb + 2] + v0.w * wa1_s[kb + 3]
                + v1.x * wa1_s[kb + 4] + v1.y * wa1_s[kb + 5]
                + v1.z * wa1_s[kb + 6] + v1.w * wa1_s[kb + 7];
            s2 += v0.x * wa2_s[kb]     + v0.y * wa2_s[kb + 1]
                + v0.z * wa2_s[kb + 2] + v0.w * wa2_s[kb + 3]
                + v1.x * wa2_s[kb + 4] + v1.y * wa2_s[kb + 5]
                + v1.z * wa2_s[kb + 6] + v1.w * wa2_s[kb + 7];
            uint32_t h0 = bfx2(v0.x, v0.y), h1 = bfx2(v0.z, v0.w);
            uint32_t h2 = bfx2(v1.x, v1.y), h3 = bfx2(v1.z, v1.w);
            uint32_t l0 = bfx2(v0.x - bf_lo_f(h0), v0.y - bf_hi_f(h0));
            uint32_t l1 = bfx2(v0.z - bf_lo_f(h1), v0.w - bf_hi_f(h1));
            uint32_t l2 = bfx2(v1.x - bf_lo_f(h2), v1.y - bf_hi_f(h2));
            uint32_t l3 = bfx2(v1.z - bf_lo_f(h3), v1.w - bf_hi_f(h3));
            uint32_t off = (uint32_t)(xrow * 128) + (((uint32_t)xc8 * 16) ^ ((xrow & 7) << 4));
            *(uint4*)(sm + H_AHI + off) = make_uint4(h0, h1, h2, h3);
            *(uint4*)(sm + H_ALO + off) = make_uint4(l0, l1, l2, l3);
        }
        __syncthreads();

        #pragma unroll
        for (int k0 = 0; k0 < 64; k0 += 16) {
            uint32_t ah[2][4], bh[8], bl[8];
            int arow = wm * 32 + (lane & 15);
            int acol = (k0 + ((lane >> 4) << 3)) * 2;
            int bj = k0 + (lane & 7) + ((lane & 8) ? 8 : 0);
            #pragma unroll
            for (int hB = 0; hB < 2; ++hB) {
                int f = wn * 32 + hB * 16 + ((lane & 16) ? 8 : 0);
                uint32_t off = ((uint32_t)bj << 9) + (((uint32_t)f * 2) ^ ((bj & 7) << 4));
                LDSM4T(bh[hB*4+0], bh[hB*4+1], bh[hB*4+2], bh[hB*4+3], sb + H_BH(s) + off);
                LDSM4T(bl[hB*4+0], bl[hB*4+1], bl[hB*4+2], bl[hB*4+3], sb + H_BL(s) + off);
            }
            #pragma unroll
            for (int mt = 0; mt < 2; ++mt) {
                uint32_t off = (uint32_t)((arow + mt * 16) * 128 + acol) ^ (uint32_t)((arow & 7) << 4);
                LDSM4(ah[mt][0], ah[mt][1], ah[mt][2], ah[mt][3], sb + H_AHI + off);
            }
            #pragma unroll
            for (int mt = 0; mt < 2; ++mt)
                #pragma unroll
                for (int nt = 0; nt < 4; ++nt) {
                    MMAB(d[mt][nt], ah[mt][0], ah[mt][1], ah[mt][2], ah[mt][3],
                         bh[nt*2], bh[nt*2+1]);
                    MMAB(d[mt][nt], ah[mt][0], ah[mt][1], ah[mt][2], ah[mt][3],
                         bl[nt*2], bl[nt*2+1]);
                }
            #pragma unroll
            for (int mt = 0; mt < 2; ++mt) {
                uint32_t off = (uint32_t)((arow + mt * 16) * 128 + acol) ^ (uint32_t)((arow & 7) << 4);
                LDSM4(ah[mt][0], ah[mt][1], ah[mt][2], ah[mt][3], sb + H_ALO + off);
            }
            #pragma unroll
            for (int mt = 0; mt < 2; ++mt)
                #pragma unroll
                for (int nt = 0; nt < 4; ++nt)
                    MMAB(d[mt][nt], ah[mt][0], ah[mt][1], ah[mt][2], ah[mt][3],
                         bh[nt*2], bh[nt*2+1]);
        }
    }

    // f1/f2 epilogue: reduce across the 8 threads of each row
    #pragma unroll
    for (int off = 1; off < 8; off <<= 1) {
        s1 += __shfl_xor_sync(0xffffffffu, s1, off);
        s2 += __shfl_xor_sync(0xffffffffu, s2, off);
    }
    if ((t & 7) == 0) {
        int r = i0 + xrow;
        g_f1[r] = s1;
        g_f2[r] = s2;
        g_e1[r] = __expf(s2);
        g_e2[r] = __expf(ALPHA * s2);
        atomicMax(&mx_s, fkey(s2));
    }

    // h epilogue
    #pragma unroll
    for (int mt = 0; mt < 2; ++mt) {
        int mg = i0 + wm * 32 + mt * 16 + (lane >> 2);
        #pragma unroll
        for (int nt = 0; nt < 4; ++nt) {
            int col = wn * 32 + nt * 8 + (lane & 3) * 2;
            half2 ph = __floats2half2_rn(d[mt][nt][0], d[mt][nt][1]);
            g_hb_hi[((size_t)mg * FO + col) >> 1] = *(uint32_t*)&ph;
            half2 qh = __floats2half2_rn(d[mt][nt][2], d[mt][nt][3]);
            g_hb_hi[((size_t)(mg + 8) * FO + col) >> 1] = *(uint32_t*)&qh;
        }
    }
    __syncthreads();
    if (t == 0) atomicMax(&g_m2b[blockIdx.x & 63], mx_s);
}

// ---------------------------------------------------------------------------
// k_attn: 296 CTAs x 256 threads, 2 CTAs/SM. Job = 64 rows x 64 j.
//  adj via cp.async smem staging. wcompute uses factored exp:
//  w = adj ? (e1>T1 ? C1*e1 : C2*e2) : enb  — 4 MUFU/call.
//  Buffers: A x2 (8K) | B x2 (32K) | adj x2 (16K, 256B swizzled rows).
// ---------------------------------------------------------------------------
#define A_OFF(p)   ((uint32_t)(p) * 8192u)
#define B_OFF(p)   (16384u + (uint32_t)(p) * 32768u)
#define ADJ_OFF(p) (81920u + (uint32_t)(p) * 16384u)
#define SMEM_C     114688

__device__ __forceinline__ void issue_B(uint32_t sb, int buf, int g, int t) {
    int jb = (g & 127) << 6;
    uint32_t stgB = sb + B_OFF(buf);
    #pragma unroll
    for (int l = 0; l < 8; ++l) {          // 2048 chunks of 16B
        int id = t + l * 256;
        int j = id >> 5, c = id & 31;
        uint32_t dst = stgB + (j << 9) + ((c * 16) ^ ((j & 7) << 4));
        const char* sh = (const char*)g_hb_hi + ((size_t)(jb + j) * FO + c * 8) * 2;
        CPA16(dst, sh);
    }
}
__device__ __forceinline__ void issue_adj(uint32_t sb, int buf,
                                          const int* __restrict__ adj, int g, int t) {
    int i0 = (g >> 7) << 6;
    int jb = (g & 127) << 6;
    uint32_t stgJ = sb + ADJ_OFF(buf);
    #pragma unroll
    for (int l = 0; l < 4; ++l) {          // 1024 chunks, 256B swizzled rows
        int id = t + l * 256;
        int r = id >> 4, c = id & 15;
        uint32_t dst = stgJ + r * 256 + ((c * 16) ^ ((r & 15) << 4));
        const void* src = adj + (size_t)(i0 + r) * NN + jb + c * 4;
        CPA16(dst, src);
    }
}

__global__ void __launch_bounds__(256, 2)
k_attn(const int* __restrict__ adj) {
    extern __shared__ char sm[];
    uint32_t sb = smem_u32(sm);

    int t    = threadIdx.x;
    int lane = t & 31, wid = t >> 5;       // wid 0..7 = N position
    int bx   = blockIdx.x;
    int st   = (bx < 104) ? bx * 56 : 5824 + (bx - 104) * 55;
    int cnt  = (bx < 104) ? 56 : 55;

    int wr = t & 63, wq = t >> 6;          // w-compute: row (0..63), j-16-group

    uint32_t mx = 0;
    #pragma unroll
    for (int i = 0; i < 64; ++i) {
        uint32_t v = g_m2b[i];
        mx = mx > v ? mx : v;
    }
    float m2 = funkey(mx);

    float d[4][4][4];
    #pragma unroll
    for (int m = 0; m < 4; ++m)
        #pragma unroll
        for (int n = 0; n < 4; ++n)
            #pragma unroll
            for (int c = 0; c < 4; ++c) d[m][n][c] = 0.f;
    float dpart = 0.f, pend[2] = {0.f, 0.f};

    auto wcompute = [&](int g, int bufA) -> float {
        uint32_t jro = (uint32_t)(wr * 256);
        uint32_t jxo = (uint32_t)((wr & 15) << 4);
        const char* adjb = sm + ADJ_OFF(bufA);
        char*       ap   = sm + A_OFF(bufA);
        float f1r = g_f1[((g >> 7) << 6) + wr];
        float bsh = fmaxf(f1r + m2, 0.f);
        float C1  = __expf(f1r - bsh);
        float C2  = __expf(ALPHA * f1r - bsh);
        float T1  = __expf(-f1r);
        float enb = __expf(MASKF - bsh);
        int4 a0 = *(const int4*)(adjb + jro + (((wq * 64) +  0) ^ jxo));
        int4 a1 = *(const int4*)(adjb + jro + (((wq * 64) + 16) ^ jxo));
        int4 a2 = *(const int4*)(adjb + jro + (((wq * 64) + 32) ^ jxo));
        int4 a3 = *(const int4*)(adjb + jro + (((wq * 64) + 48) ^ jxo));
        int jq = ((g & 127) << 6) + wq * 16;
        int av[16] = {a0.x,a0.y,a0.z,a0.w, a1.x,a1.y,a1.z,a1.w,
                      a2.x,a2.y,a2.z,a2.w, a3.x,a3.y,a3.z,a3.w};
        float dsum = 0.f;
        uint32_t hi[8];
        #pragma unroll
        for (int p = 0; p < 4; ++p) {
            float4 e1q = *(const float4*)(g_e1 + jq + 4 * p);
            float4 e2q = *(const float4*)(g_e2 + jq + 4 * p);
            float w0 = (av[4*p+0] > 0) ? (e1q.x > T1 ? C1 * e1q.x : C2 * e2q.x) : enb;
            float w1 = (av[4*p+1] > 0) ? (e1q.y > T1 ? C1 * e1q.y : C2 * e2q.y) : enb;
            float w2 = (av[4*p+2] > 0) ? (e1q.z > T1 ? C1 * e1q.z : C2 * e2q.z) : enb;
            float w3 = (av[4*p+3] > 0) ? (e1q.w > T1 ? C1 * e1q.w : C2 * e2q.w) : enb;
            half2 h0 = __floats2half2_rn(w0, w1);
            half2 h1 = __floats2half2_rn(w2, w3);
            hi[2*p]   = *(uint32_t*)&h0;
            hi[2*p+1] = *(uint32_t*)&h1;
            dsum += __low2float(h0) + __high2float(h0)
                  + __low2float(h1) + __high2float(h1);
        }
        uint32_t base = (uint32_t)(wr * 128 + wq * 32);
        uint32_t xo   = (uint32_t)((wr & 7) << 4);
        *(uint4*)(ap + (base ^ xo))        = make_uint4(hi[0], hi[1], hi[2], hi[3]);
        *(uint4*)(ap + ((base + 16) ^ xo)) = make_uint4(hi[4], hi[5], hi[6], hi[7]);
        return dsum;
    };

    // ---- prologue ----
    issue_B(sb, 0, st, t);
    issue_adj(sb, 0, adj, st, t);
    if (cnt > 1) issue_adj(sb, 1, adj, st + 1, t);
    CPA_COMMIT();
    CPA_WAITG(0);
    __syncthreads();
    pend[0] = wcompute(st, 0);

    for (int u = 0; u < cnt; ++u) {
        CPA_WAITG(0);
        __syncthreads();                   // A(u), B(u), adj(u+1) ready

        if (u + 1 < cnt) issue_B(sb, (u + 1) & 1, st + u + 1, t);
        if (u + 2 < cnt) issue_adj(sb, u & 1, adj, st + u + 2, t);
        CPA_COMMIT();
        if (u + 1 < cnt) pend[(u + 1) & 1] = wcompute(st + u + 1, (u + 1) & 1);

        // ---- mma(u): A[u&1], B[u&1] ----
        uint32_t stgA = sb + A_OFF(u & 1);
        uint32_t stgB = sb + B_OFF(u & 1);
        #pragma unroll
        for (int k0 = 0; k0 < KT; k0 += 16) {
            uint32_t ah[4][4], bh[8];
            int arow = lane & 15;
            int acol = (k0 + ((lane >> 4) << 3)) * 2;
            int bj = k0 + (lane & 7) + ((lane & 8) ? 8 : 0);
            #pragma unroll
            for (int hB = 0; hB < 2; ++hB) {
                int f = wid * 32 + hB * 16 + ((lane & 16) ? 8 : 0);
                uint32_t off = ((uint32_t)bj << 9) + (((uint32_t)f * 2) ^ ((bj & 7) << 4));
                LDSM4T(bh[hB*4+0], bh[hB*4+1], bh[hB*4+2], bh[hB*4+3], stgB + off);
            }
            #pragma unroll
            for (int mt = 0; mt < 4; ++mt) {
                uint32_t off = (uint32_t)((arow + mt * 16) * 128 + acol) ^ (uint32_t)((arow & 7) << 4);
                LDSM4(ah[mt][0], ah[mt][1], ah[mt][2], ah[mt][3], stgA + off);
            }
            #pragma unroll
            for (int mt = 0; mt < 4; ++mt)
                #pragma unroll
                for (int nt = 0; nt < 4; ++nt)
                    MMAH(d[mt][nt], ah[mt][0], ah[mt][1], ah[mt][2], ah[mt][3],
                         bh[nt*2], bh[nt*2+1]);
        }

        // ---- denom bookkeeping + flush on rb boundary / end ----
        dpart += pend[u & 1];
        int g = st + u;
        bool lastu = (u == cnt - 1);
        if (lastu || (((g + 1) >> 7) != (g >> 7))) {
            int rb   = g >> 7;
            int part = bx - first_cta_of(rb << 7);
            int i0   = rb << 6;
            atomicAdd(&g_pd[(size_t)part * NN + i0 + wr], dpart);
            dpart = 0.f;
            float* basep = g_pn + (size_t)part * NN * FO;
            #pragma unroll
            for (int mt = 0; mt < 4; ++mt) {
                int m = mt * 16 + (lane >> 2);
                #pragma unroll
                for (int nt = 0; nt < 4; ++nt) {
                    int col = wid * 32 + nt * 8 + (lane & 3) * 2;
                    float* dst = basep + (size_t)(i0 + m) * FO + col;
                    *(float2*)dst            = make_float2(d[mt][nt][0], d[mt][nt][1]);
                    *(float2*)(dst + 8 * FO) = make_float2(d[mt][nt][2], d[mt][nt][3]);
                    d[mt][nt][0] = 0.f; d[mt][nt][1] = 0.f;
                    d[mt][nt][2] = 0.f; d[mt][nt][3] = 0.f;
                }
            }
        }
    }
}

// ---------------------------------------------------------------------------
// k_norm: sum only the partials that have writers for this 64-row block
// ---------------------------------------------------------------------------
__global__ void k_norm(float* __restrict__ out) {
    int idx = blockIdx.x * 256 + threadIdx.x;    // float4 id
    int row = idx >> 6;
    int T0  = (row >> 6) << 7;                   // first job of this rb64
    int np  = first_cta_of(T0 + 127) - first_cta_of(T0) + 1;  // <= NPART
    float4 acc = make_float4(0.f, 0.f, 0.f, 0.f);
    float den = 0.f;
    for (int p = 0; p < np; ++p) {
        float4 v = ((const float4*)(g_pn + (size_t)p * NN * FO))[idx];
        acc.x += v.x; acc.y += v.y; acc.z += v.z; acc.w += v.w;
        den += g_pd[(size_t)p * NN + row];
    }
    float inv = 1.f / den;
    ((float4*)out)[idx] = make_float4(acc.x * inv, acc.y * inv,
                                      acc.z * inv, acc.w * inv);
}

// ---------------------------------------------------------------------------
extern "C" void kernel_launch(void* const* d_in, const int* in_sizes, int n_in,
                              void* d_out, int out_size) {
    const float* x   = (const float*)d_in[0];
    const int*   adj = (const int*)  d_in[1];
    const float* W   = (const float*)d_in[2];
    const float* a   = (const float*)d_in[3];
    float*       out = (float*)d_out;

    cudaFuncSetAttribute(k_h_mma, cudaFuncAttributeMaxDynamicSharedMemorySize, SMEM_H);
    cudaFuncSetAttribute(k_attn,  cudaFuncAttributeMaxDynamicSharedMemorySize, SMEM_C);

    k_conv <<<256, 256>>>(W, a);
    k_h_mma<<<128, 512, SMEM_H>>>(x);
    k_attn <<<296, 256, SMEM_C>>>(adj);
    k_norm <<<2048, 256>>>(out);
}